// round 2
// baseline (speedup 1.0000x reference)
#include <cuda_runtime.h>
#include <math.h>

// Problem constants (shapes fixed by the reference)
#define NMAX 100000
#define EMAX 1600000

#define NEG_INF __int_as_float(0xff800000)

// ---- scratch (device globals: allocation-free rule) ----
__device__ float g_xl[(size_t)NMAX * 128];   // source transform, current layer
__device__ float g_xr[(size_t)NMAX * 128];   // target transform, current layer
__device__ float g_h [(size_t)NMAX * 64];    // node features between layers
__device__ int   g_deg[NMAX];                // degree, then scatter cursor
__device__ int   g_rowptr[NMAX + 1];
__device__ int   g_ceid[EMAX];               // edge id in CSR-by-dst order
__device__ int   g_csrc[EMAX];               // src node in CSR-by-dst order

// ---------------- CSR build ----------------

__global__ void zero_kernel(int n) {
    int i = blockIdx.x * blockDim.x + threadIdx.x;
    if (i < n) g_deg[i] = 0;
}

__global__ void hist_kernel(const int* __restrict__ dst, int ne) {
    int i = blockIdx.x * blockDim.x + threadIdx.x;
    if (i < ne) atomicAdd(&g_deg[dst[i]], 1);
}

// single-block exclusive scan over g_deg -> g_rowptr; resets g_deg to 0 (cursor)
__global__ void scan_kernel(int n, int ne) {
    __shared__ int ss[1024];
    int t = threadIdx.x;
    int per = (n + 1023) >> 10;
    int lo = t * per;
    int hi = lo + per; if (hi > n) hi = n;
    int s = 0;
    for (int i = lo; i < hi; i++) s += g_deg[i];
    ss[t] = s;
    __syncthreads();
    for (int off = 1; off < 1024; off <<= 1) {
        int v = (t >= off) ? ss[t - off] : 0;
        __syncthreads();
        ss[t] += v;
        __syncthreads();
    }
    int run = (t == 0) ? 0 : ss[t - 1];
    for (int i = lo; i < hi; i++) {
        run += g_deg[i];
        g_rowptr[i] = run - g_deg[i];
        g_deg[i] = 0;                       // becomes scatter cursor
    }
    if (t == 0) g_rowptr[n] = ne;
}

__global__ void scatter_kernel(const int* __restrict__ src,
                               const int* __restrict__ dst, int ne) {
    int i = blockIdx.x * blockDim.x + threadIdx.x;
    if (i < ne) {
        int d = dst[i];
        int pos = g_rowptr[d] + atomicAdd(&g_deg[d], 1);
        g_ceid[pos] = i;
        g_csrc[pos] = src[i];
    }
}

// ---------------- node GEMM: out = act(in) @ W + b ----------------
// 64 nodes per block, thread computes 8 nodes x NC cols, W streamed via L1.

template <int K>
__device__ __forceinline__ void ldvec(const float* p, float* v) {
    if constexpr (K == 4) {
        float4 t = __ldg((const float4*)p);
        v[0] = t.x; v[1] = t.y; v[2] = t.z; v[3] = t.w;
    } else {
        float2 t = __ldg((const float2*)p);
        v[0] = t.x; v[1] = t.y;
    }
}

template <int NC>
__global__ void __launch_bounds__(256)
gemm_kernel(const float* __restrict__ ext, int insel, int fin,
            const float* __restrict__ W, const float* __restrict__ bias,
            int outsel, int n) {
    const float* in = insel ? g_h : ext;
    float* out = outsel ? g_xr : g_xl;
    const int wout = 32 * NC;
    __shared__ float xs[64][81];
    int n0 = blockIdx.x * 64;

    for (int idx = threadIdx.x; idx < 64 * fin; idx += 256) {
        int nl = idx / fin, f = idx - nl * fin;
        float v = 0.f;
        int nd = n0 + nl;
        if (nd < n) v = in[(size_t)nd * fin + f];
        if (insel) v = (v > 0.f) ? v : 0.01f * v;   // inter-layer leaky_relu(0.01)
        xs[nl][f] = v;
    }
    __syncthreads();

    int r = threadIdx.x >> 5, c = threadIdx.x & 31;
    float acc[8][NC];
#pragma unroll
    for (int j = 0; j < 8; j++)
#pragma unroll
        for (int k = 0; k < NC; k++) acc[j][k] = 0.f;

    for (int f = 0; f < fin; f++) {
        float wv[NC];
        ldvec<NC>(W + (size_t)f * wout + c * NC, wv);
#pragma unroll
        for (int j = 0; j < 8; j++) {
            float a = xs[r * 8 + j][f];
#pragma unroll
            for (int k = 0; k < NC; k++) acc[j][k] = fmaf(a, wv[k], acc[j][k]);
        }
    }
#pragma unroll
    for (int j = 0; j < 8; j++) {
        int nd = n0 + r * 8 + j;
        if (nd < n) {
#pragma unroll
            for (int k = 0; k < NC; k++)
                out[(size_t)nd * wout + c * NC + k] = acc[j][k] + __ldg(&bias[c * NC + k]);
        }
    }
}

// ---------------- fused GATv2 edge+softmax+aggregate (node-centric) ----------------
// warp per node; lanes split channels (K per lane); online softmax over CSR edge
// chunks of <=32 (per-edge logit/src parked in lane-j registers, no smem, no atomics).

template <int K, bool CONCAT>
__global__ void agg_kernel(const float* __restrict__ edge_attr,
                           const float* __restrict__ We,
                           const float* __restrict__ att,
                           const float* __restrict__ bias,
                           float* __restrict__ extout, int out_ext, int n) {
    constexpr int WD = 32 * K;       // H*C total width
    const unsigned FULL = 0xffffffffu;
    int lane = threadIdx.x & 31;
    int warp = threadIdx.x >> 5;

    // edge-feature weights + attention vector resident in registers
    float wreg[10][K];
#pragma unroll
    for (int f = 0; f < 10; f++)
#pragma unroll
        for (int k = 0; k < K; k++)
            wreg[f][k] = __ldg(&We[f * WD + lane * K + k]);
    float areg[K];
#pragma unroll
    for (int k = 0; k < K; k++) areg[k] = __ldg(&att[lane * K + k]);

    bool head1 = (lane >= 16);
    float* outp = out_ext ? extout : g_h;

    for (int node = blockIdx.x * 8 + warp; node < n; node += gridDim.x * 8) {
        int s0 = g_rowptr[node], s1 = g_rowptr[node + 1];
        float xrv[K];
        ldvec<K>(g_xr + (size_t)node * WD + lane * K, xrv);

        float acc[K];
#pragma unroll
        for (int k = 0; k < K; k++) acc[k] = 0.f;
        float mh = NEG_INF;
        float ssum = 0.f;

        for (int base = s0; base < s1; base += 32) {
            int cn = s1 - base; if (cn > 32) cn = 32;
            float rl0 = 0.f, rl1 = 0.f;
            int rs = 0;

            // phase A: per-edge GATv2 logits (whole warp per edge; lane j keeps edge j)
            for (int j = 0; j < cn; j++) {
                int e   = __ldg(&g_ceid[base + j]);
                int src = __ldg(&g_csrc[base + j]);
                // edge_attr row: 10 floats, 8B-aligned -> 5x float2
                const float2* ea2 = (const float2*)(edge_attr + (size_t)e * 10);
                float ev[10];
#pragma unroll
                for (int f2 = 0; f2 < 5; f2++) {
                    float2 t = __ldg(&ea2[f2]);
                    ev[f2 * 2] = t.x; ev[f2 * 2 + 1] = t.y;
                }
                float ef[K];
#pragma unroll
                for (int k = 0; k < K; k++) ef[k] = 0.f;
#pragma unroll
                for (int f = 0; f < 10; f++) {
#pragma unroll
                    for (int k = 0; k < K; k++) ef[k] = fmaf(ev[f], wreg[f][k], ef[k]);
                }
                float xv[K];
                ldvec<K>(g_xl + (size_t)src * WD + lane * K, xv);
                float p = 0.f;
#pragma unroll
                for (int k = 0; k < K; k++) {
                    float m = xv[k] + xrv[k] + ef[k];
                    m = fmaxf(m, 0.f) + 0.2f * fminf(m, 0.f);  // leaky_relu(0.2)
                    p = fmaf(m, areg[k], p);
                }
                // per-head reduce over 16-lane halves
                p += __shfl_down_sync(FULL, p, 8, 16);
                p += __shfl_down_sync(FULL, p, 4, 16);
                p += __shfl_down_sync(FULL, p, 2, 16);
                p += __shfl_down_sync(FULL, p, 1, 16);
                float l0 = __shfl_sync(FULL, p, 0);
                float l1 = __shfl_sync(FULL, p, 16);
                if (lane == j) { rl0 = l0; rl1 = l1; rs = src; }
            }

            // chunk max per head + online rescale
            float v0 = (lane < cn) ? rl0 : NEG_INF;
            float v1 = (lane < cn) ? rl1 : NEG_INF;
#pragma unroll
            for (int off = 16; off > 0; off >>= 1) {
                v0 = fmaxf(v0, __shfl_xor_sync(FULL, v0, off));
                v1 = fmaxf(v1, __shfl_xor_sync(FULL, v1, off));
            }
            float mold = mh;
            mh = fmaxf(mh, head1 ? v1 : v0);
            float sc = __expf(mold - mh);   // exp(-inf)=0 on first chunk
            ssum *= sc;
#pragma unroll
            for (int k = 0; k < K; k++) acc[k] *= sc;

            // phase B: weighted aggregation of xl[src]
            for (int j = 0; j < cn; j++) {
                int src = __shfl_sync(FULL, rs, j);
                float l0 = __shfl_sync(FULL, rl0, j);
                float l1 = __shfl_sync(FULL, rl1, j);
                float w = __expf((head1 ? l1 : l0) - mh);
                ssum += w;
                float xv[K];
                ldvec<K>(g_xl + (size_t)src * WD + lane * K, xv);
#pragma unroll
                for (int k = 0; k < K; k++) acc[k] = fmaf(w, xv[k], acc[k]);
            }
        }

        float inv = 1.f / fmaxf(ssum, 1e-16f);
        if constexpr (CONCAT) {
#pragma unroll
            for (int k = 0; k < K; k++)
                outp[(size_t)node * WD + lane * K + k] =
                    acc[k] * inv + __ldg(&bias[lane * K + k]);
        } else {
            float o[K];
#pragma unroll
            for (int k = 0; k < K; k++) {
                o[k] = acc[k] * inv;
                o[k] = 0.5f * (o[k] + __shfl_xor_sync(FULL, o[k], 16));  // head mean
            }
            if (lane < 16) {
#pragma unroll
                for (int k = 0; k < K; k++)
                    outp[(size_t)node * (WD / 2) + lane * K + k] =
                        o[k] + __ldg(&bias[lane * K + k]);
            }
        }
    }
}

// ---------------- launch ----------------

extern "C" void kernel_launch(void* const* d_in, const int* in_sizes, int n_in,
                              void* d_out, int out_size) {
    const float* x     = (const float*)d_in[0];
    const int*   ei    = (const int*)  d_in[1];
    const float* ea    = (const float*)d_in[2];
    const float* Wl0   = (const float*)d_in[3];
    const float* bl0   = (const float*)d_in[4];
    const float* Wr0   = (const float*)d_in[5];
    const float* br0   = (const float*)d_in[6];
    const float* We0   = (const float*)d_in[7];
    const float* att0  = (const float*)d_in[8];
    const float* bias0 = (const float*)d_in[9];
    const float* Wl1   = (const float*)d_in[10];
    const float* bl1   = (const float*)d_in[11];
    const float* Wr1   = (const float*)d_in[12];
    const float* br1   = (const float*)d_in[13];
    const float* We1   = (const float*)d_in[14];
    const float* att1  = (const float*)d_in[15];
    const float* bias1 = (const float*)d_in[16];
    float* out = (float*)d_out;

    int n  = in_sizes[0] / 79;    // nodes
    int ne = in_sizes[1] / 2;     // edges
    const int* srcp = ei;
    const int* dstp = ei + ne;

    // CSR by destination (rebuilt every call; no caching)
    zero_kernel   <<<(n  + 255) / 256, 256>>>(n);
    hist_kernel   <<<(ne + 255) / 256, 256>>>(dstp, ne);
    scan_kernel   <<<1, 1024>>>(n, ne);
    scatter_kernel<<<(ne + 255) / 256, 256>>>(srcp, dstp, ne);

    int gb = (n + 63) / 64;

    // layer 0: 79 -> 2x32 concat (width 64)
    gemm_kernel<2><<<gb, 256>>>(x, 0, 79, Wl0, bl0, 0, n);
    gemm_kernel<2><<<gb, 256>>>(x, 0, 79, Wr0, br0, 1, n);
    agg_kernel<2, true><<<2048, 256>>>(ea, We0, att0, bias0, out, 0, n);

    // layers 1,2: 64 -> 2x64 mean (width 64), leaky_relu(0.01) on input inside gemm
    for (int i = 0; i < 2; i++) {
        gemm_kernel<4><<<gb, 256>>>(nullptr, 1, 64, Wl1 + (size_t)i * 64 * 128,
                                    bl1 + i * 128, 0, n);
        gemm_kernel<4><<<gb, 256>>>(nullptr, 1, 64, Wr1 + (size_t)i * 64 * 128,
                                    br1 + i * 128, 1, n);
        agg_kernel<4, false><<<2048, 256>>>(ea, We1 + (size_t)i * 10 * 128,
                                            att1 + i * 2 * 64, bias1 + i * 64,
                                            out, (i == 1) ? 1 : 0, n);
    }
}

// round 4
// speedup vs baseline: 1.0775x; 1.0775x over previous
#include <cuda_runtime.h>
#include <math.h>

// Problem constants (shapes fixed by the reference)
#define NMAX 100000
#define EMAX 1600000

#define NEG_INF __int_as_float(0xff800000)

// ---- scratch (device globals: allocation-free rule) ----
__device__ float g_xl[(size_t)NMAX * 128];   // source transform, current layer
__device__ float g_xr[(size_t)NMAX * 128];   // target transform, current layer
__device__ float g_h [(size_t)NMAX * 64];    // node features between layers
__device__ int   g_deg[NMAX];                // degree, then scatter cursor
__device__ int   g_rowptr[NMAX + 1];
__device__ int2  g_epack[EMAX];              // (edge id, src node) in CSR-by-dst order

// ---------------- CSR build ----------------

__global__ void zero_kernel(int n) {
    int i = blockIdx.x * blockDim.x + threadIdx.x;
    if (i < n) g_deg[i] = 0;
}

__global__ void hist_kernel(const int* __restrict__ dst, int ne) {
    int i = blockIdx.x * blockDim.x + threadIdx.x;
    if (i < ne) atomicAdd(&g_deg[dst[i]], 1);
}

// single-block exclusive scan over g_deg -> g_rowptr; resets g_deg to 0 (cursor)
__global__ void scan_kernel(int n, int ne) {
    __shared__ int ss[1024];
    int t = threadIdx.x;
    int per = (n + 1023) >> 10;
    int lo = t * per;
    int hi = lo + per; if (hi > n) hi = n;
    int s = 0;
    for (int i = lo; i < hi; i++) s += g_deg[i];
    ss[t] = s;
    __syncthreads();
    for (int off = 1; off < 1024; off <<= 1) {
        int v = (t >= off) ? ss[t - off] : 0;
        __syncthreads();
        ss[t] += v;
        __syncthreads();
    }
    int run = (t == 0) ? 0 : ss[t - 1];
    for (int i = lo; i < hi; i++) {
        run += g_deg[i];
        g_rowptr[i] = run - g_deg[i];
        g_deg[i] = 0;                       // becomes scatter cursor
    }
    if (t == 0) g_rowptr[n] = ne;
}

__global__ void scatter_kernel(const int* __restrict__ src,
                               const int* __restrict__ dst, int ne) {
    int i = blockIdx.x * blockDim.x + threadIdx.x;
    if (i < ne) {
        int d = dst[i];
        int pos = g_rowptr[d] + atomicAdd(&g_deg[d], 1);
        g_epack[pos] = make_int2(i, src[i]);
    }
}

// ---------------- node GEMM: out = act(in) @ W + b ----------------
// 64 nodes per block, thread computes 8 nodes x NC cols, W streamed via L1.

template <int K>
__device__ __forceinline__ void ldvec(const float* p, float* v) {
    if constexpr (K == 4) {
        float4 t = __ldg((const float4*)p);
        v[0] = t.x; v[1] = t.y; v[2] = t.z; v[3] = t.w;
    } else {
        float2 t = __ldg((const float2*)p);
        v[0] = t.x; v[1] = t.y;
    }
}

template <int NC>
__global__ void __launch_bounds__(256)
gemm_kernel(const float* __restrict__ ext, int insel, int fin,
            const float* __restrict__ W, const float* __restrict__ bias,
            int outsel, int n) {
    const float* in = insel ? g_h : ext;
    float* out = outsel ? g_xr : g_xl;
    const int wout = 32 * NC;
    __shared__ float xs[64][81];
    int n0 = blockIdx.x * 64;

    for (int idx = threadIdx.x; idx < 64 * fin; idx += 256) {
        int nl = idx / fin, f = idx - nl * fin;
        float v = 0.f;
        int nd = n0 + nl;
        if (nd < n) v = in[(size_t)nd * fin + f];
        if (insel) v = (v > 0.f) ? v : 0.01f * v;   // inter-layer leaky_relu(0.01)
        xs[nl][f] = v;
    }
    __syncthreads();

    int r = threadIdx.x >> 5, c = threadIdx.x & 31;
    float acc[8][NC];
#pragma unroll
    for (int j = 0; j < 8; j++)
#pragma unroll
        for (int k = 0; k < NC; k++) acc[j][k] = 0.f;

    for (int f = 0; f < fin; f++) {
        float wv[NC];
        ldvec<NC>(W + (size_t)f * wout + c * NC, wv);
#pragma unroll
        for (int j = 0; j < 8; j++) {
            float a = xs[r * 8 + j][f];
#pragma unroll
            for (int k = 0; k < NC; k++) acc[j][k] = fmaf(a, wv[k], acc[j][k]);
        }
    }
#pragma unroll
    for (int j = 0; j < 8; j++) {
        int nd = n0 + r * 8 + j;
        if (nd < n) {
#pragma unroll
            for (int k = 0; k < NC; k++)
                out[(size_t)nd * wout + c * NC + k] = acc[j][k] + __ldg(&bias[c * NC + k]);
        }
    }
}

// ---------------- fused GATv2 edge+softmax+aggregate (node-centric) ----------------
// warp per node; lanes split channels (K per lane, lanes 0-15 = head0, 16-31 = head1).
// Per-edge ONLINE softmax: logits reduced via 4x shfl_xor(width=16), after which every
// lane holds its own head's logit; xl[src] gathered ONCE and consumed immediately.

template <int K, bool CONCAT>
__global__ void __launch_bounds__(256)
agg_kernel(const float* __restrict__ edge_attr,
           const float* __restrict__ We,
           const float* __restrict__ att,
           const float* __restrict__ bias,
           float* __restrict__ extout, int out_ext, int n) {
    constexpr int WD = 32 * K;       // H*C total width
    const unsigned FULL = 0xffffffffu;
    int lane = threadIdx.x & 31;
    int warp = threadIdx.x >> 5;

    // edge-feature weights + attention vector resident in registers
    float wreg[10][K];
#pragma unroll
    for (int f = 0; f < 10; f++)
#pragma unroll
        for (int k = 0; k < K; k++)
            wreg[f][k] = __ldg(&We[f * WD + lane * K + k]);
    float areg[K];
#pragma unroll
    for (int k = 0; k < K; k++) areg[k] = __ldg(&att[lane * K + k]);

    float* outp = out_ext ? extout : g_h;

    for (int node = blockIdx.x * 8 + warp; node < n; node += gridDim.x * 8) {
        int s0 = g_rowptr[node], s1 = g_rowptr[node + 1];
        float xrv[K];
        ldvec<K>(g_xr + (size_t)node * WD + lane * K, xrv);

        float acc[K];
#pragma unroll
        for (int k = 0; k < K; k++) acc[k] = 0.f;
        float mh = NEG_INF;
        float ssum = 0.f;

#pragma unroll 2
        for (int p0 = s0; p0 < s1; p0++) {
            int2 es = __ldg(&g_epack[p0]);            // (edge id, src)
            // edge_attr row: 10 floats, 8B-aligned -> 5x float2 (warp-broadcast)
            const float2* ea2 = (const float2*)(edge_attr + (size_t)es.x * 10);
            float ev[10];
#pragma unroll
            for (int f2 = 0; f2 < 5; f2++) {
                float2 t = __ldg(&ea2[f2]);
                ev[f2 * 2] = t.x; ev[f2 * 2 + 1] = t.y;
            }
            float xv[K];
            ldvec<K>(g_xl + (size_t)es.y * WD + lane * K, xv);

            float ef[K];
#pragma unroll
            for (int k = 0; k < K; k++) ef[k] = 0.f;
#pragma unroll
            for (int f = 0; f < 10; f++)
#pragma unroll
                for (int k = 0; k < K; k++) ef[k] = fmaf(ev[f], wreg[f][k], ef[k]);

            float p = 0.f;
#pragma unroll
            for (int k = 0; k < K; k++) {
                float m = xv[k] + xrv[k] + ef[k];
                m = fmaxf(m, 0.f) + 0.2f * fminf(m, 0.f);  // leaky_relu(0.2)
                p = fmaf(m, areg[k], p);
            }
            // per-head reduce: every lane ends with its own head's logit
            p += __shfl_xor_sync(FULL, p, 1, 16);
            p += __shfl_xor_sync(FULL, p, 2, 16);
            p += __shfl_xor_sync(FULL, p, 4, 16);
            p += __shfl_xor_sync(FULL, p, 8, 16);

            // online softmax update (xv consumed from registers, no second gather)
            float mnew = fmaxf(mh, p);
            float sc = __expf(mh - mnew);     // 0 on first edge (mh = -inf)
            float w  = __expf(p - mnew);
            ssum = ssum * sc + w;
#pragma unroll
            for (int k = 0; k < K; k++) acc[k] = fmaf(acc[k], sc, w * xv[k]);
            mh = mnew;
        }

        float inv = 1.f / fmaxf(ssum, 1e-16f);
        if constexpr (CONCAT) {
#pragma unroll
            for (int k = 0; k < K; k++)
                outp[(size_t)node * WD + lane * K + k] =
                    acc[k] * inv + __ldg(&bias[lane * K + k]);
        } else {
            float o[K];
#pragma unroll
            for (int k = 0; k < K; k++) {
                o[k] = acc[k] * inv;
                o[k] = 0.5f * (o[k] + __shfl_xor_sync(FULL, o[k], 16));  // head mean
            }
            if (lane < 16) {
#pragma unroll
                for (int k = 0; k < K; k++)
                    outp[(size_t)node * (WD / 2) + lane * K + k] =
                        o[k] + __ldg(&bias[lane * K + k]);
            }
        }
    }
}

// ---------------- launch ----------------

extern "C" void kernel_launch(void* const* d_in, const int* in_sizes, int n_in,
                              void* d_out, int out_size) {
    const float* x     = (const float*)d_in[0];
    const int*   ei    = (const int*)  d_in[1];
    const float* ea    = (const float*)d_in[2];
    const float* Wl0   = (const float*)d_in[3];
    const float* bl0   = (const float*)d_in[4];
    const float* Wr0   = (const float*)d_in[5];
    const float* br0   = (const float*)d_in[6];
    const float* We0   = (const float*)d_in[7];
    const float* att0  = (const float*)d_in[8];
    const float* bias0 = (const float*)d_in[9];
    const float* Wl1   = (const float*)d_in[10];
    const float* bl1   = (const float*)d_in[11];
    const float* Wr1   = (const float*)d_in[12];
    const float* br1   = (const float*)d_in[13];
    const float* We1   = (const float*)d_in[14];
    const float* att1  = (const float*)d_in[15];
    const float* bias1 = (const float*)d_in[16];
    float* out = (float*)d_out;

    int n  = in_sizes[0] / 79;    // nodes
    int ne = in_sizes[1] / 2;     // edges
    const int* srcp = ei;
    const int* dstp = ei + ne;

    // CSR by destination (rebuilt every call; no caching)
    zero_kernel   <<<(n  + 255) / 256, 256>>>(n);
    hist_kernel   <<<(ne + 255) / 256, 256>>>(dstp, ne);
    scan_kernel   <<<1, 1024>>>(n, ne);
    scatter_kernel<<<(ne + 255) / 256, 256>>>(srcp, dstp, ne);

    int gb = (n + 63) / 64;

    // layer 0: 79 -> 2x32 concat (width 64)
    gemm_kernel<2><<<gb, 256>>>(x, 0, 79, Wl0, bl0, 0, n);
    gemm_kernel<2><<<gb, 256>>>(x, 0, 79, Wr0, br0, 1, n);
    agg_kernel<2, true><<<4096, 256>>>(ea, We0, att0, bias0, out, 0, n);

    // layers 1,2: 64 -> 2x64 mean (width 64), leaky_relu(0.01) on input inside gemm
    for (int i = 0; i < 2; i++) {
        gemm_kernel<4><<<gb, 256>>>(nullptr, 1, 64, Wl1 + (size_t)i * 64 * 128,
                                    bl1 + i * 128, 0, n);
        gemm_kernel<4><<<gb, 256>>>(nullptr, 1, 64, Wr1 + (size_t)i * 64 * 128,
                                    br1 + i * 128, 1, n);
        agg_kernel<4, false><<<4096, 256>>>(ea, We1 + (size_t)i * 10 * 128,
                                            att1 + i * 2 * 64, bias1 + i * 64,
                                            out, (i == 1) ? 1 : 0, n);
    }
}